// round 4
// baseline (speedup 1.0000x reference)
#include <cuda_runtime.h>
#include <math.h>

#define NN      256      // neurons
#define NSAMP   512      // samples
#define NROUND  32       // MAX_SPIKES rounds
#define NSTEP   32       // RK4 steps per round

// flattened output offsets (all float32)
#define OUT_TIMES 0
#define OUT_VALS  (NSAMP * NROUND)                       // 16384
#define OUT_MARKS (OUT_VALS + NSAMP * NROUND * NN * 3)   // 12599296

__global__ __launch_bounds__(NN)
void snn_kernel(const float* __restrict__ ic,      // [256]
                const float* __restrict__ w,       // [256,256]
                const float* __restrict__ mu,      // [2]
                const float* __restrict__ v0g,     // [256]
                const float* __restrict__ i0g,     // [256]
                const float* __restrict__ s0g,     // [512,256]
                const float* __restrict__ reset_s, // [32,512,256]
                const int*   __restrict__ t1p,     // scalar
                float* __restrict__ out)
{
    const int samp = blockIdx.x;
    const int n    = threadIdx.x;
    const int lane = n & 31;
    const int wid  = n >> 5;

    __shared__ float sh_v[8], sh_p[8];
    __shared__ int   sh_i[8];
    __shared__ float sh_frac, sh_tev;
    __shared__ int   sh_trig;
    __shared__ int   sh_eidx;

    const float t1f = (float)(*t1p);
    const float mu1 = mu[0];
    const float mu2 = mu[1];
    const float icn = ic[n];

    float v  = v0g[n];
    float iC = i0g[n];
    float s  = s0g[samp * NN + n];
    float t0s = 0.0f;

    for (int k = 0; k < NROUND; ++k) {
        const float dt = (t1f - t0s) * (1.0f / (float)NSTEP);
        bool  done = false;
        float tev  = t1f;
        float yv = v, yi = iC, ys = s;
        bool  em = false;

        if (dt > 0.0f) {
            float tcur = t0s;
            const float h  = dt;
            const float hh = 0.5f * h;
            const float h6 = h * (1.0f / 6.0f);
            for (int st = 0; st < NSTEP; ++st) {
                // ---- RK4 step (s does not feed back into v,i) ----
                float dv1 = mu1 * (iC + icn - v);
                float di1 = -mu2 * iC;
                float ds1 = 1.0f / (1.0f + expf(-v));
                float v2 = v + hh * dv1, i2 = iC + hh * di1;
                float dv2 = mu1 * (i2 + icn - v2);
                float di2 = -mu2 * i2;
                float ds2 = 1.0f / (1.0f + expf(-v2));
                float v3 = v + hh * dv2, i3 = iC + hh * di2;
                float dv3 = mu1 * (i3 + icn - v3);
                float di3 = -mu2 * i3;
                float ds3 = 1.0f / (1.0f + expf(-v3));
                float v4 = v + h * dv3, i4 = iC + h * di3;
                float dv4 = mu1 * (i4 + icn - v4);
                float di4 = -mu2 * i4;
                float ds4 = 1.0f / (1.0f + expf(-v4));
                float vn  = v  + h6 * (dv1 + 2.0f * dv2 + 2.0f * dv3 + dv4);
                float in2 = iC + h6 * (di1 + 2.0f * di2 + 2.0f * di3 + di4);
                float sn2 = s  + h6 * (ds1 + 2.0f * ds2 + 2.0f * ds3 + ds4);

                // ---- block argmax of sn2 (payload: s_prev, idx; ties -> lower idx) ----
                float rv = sn2, rp = s;
                int   ri = n;
                #pragma unroll
                for (int o = 16; o > 0; o >>= 1) {
                    float ov = __shfl_down_sync(0xffffffffu, rv, o);
                    float op = __shfl_down_sync(0xffffffffu, rp, o);
                    int   oi = __shfl_down_sync(0xffffffffu, ri, o);
                    if (ov > rv || (ov == rv && oi < ri)) { rv = ov; rp = op; ri = oi; }
                }
                if (lane == 0) { sh_v[wid] = rv; sh_p[wid] = rp; sh_i[wid] = ri; }
                __syncthreads();
                if (wid == 0) {
                    float rv2 = (lane < 8) ? sh_v[lane] : -INFINITY;
                    float rp2 = (lane < 8) ? sh_p[lane] : 0.0f;
                    int   ri2 = (lane < 8) ? sh_i[lane] : NN;
                    #pragma unroll
                    for (int o = 4; o > 0; o >>= 1) {
                        float ov = __shfl_down_sync(0xffffffffu, rv2, o);
                        float op = __shfl_down_sync(0xffffffffu, rp2, o);
                        int   oi = __shfl_down_sync(0xffffffffu, ri2, o);
                        if (ov > rv2 || (ov == rv2 && oi < ri2)) { rv2 = ov; rp2 = op; ri2 = oi; }
                    }
                    if (lane == 0) {
                        int trig = (rv2 > 0.0f);
                        sh_trig = trig;
                        if (trig) {
                            float frac = rp2 / (rp2 - rv2 + 1e-12f);
                            frac = fminf(fmaxf(frac, 0.0f), 1.0f);
                            sh_frac = frac;
                            sh_tev  = tcur + frac * dt;
                        }
                    }
                }
                __syncthreads();
                if (sh_trig) {   // block-uniform
                    float frac = sh_frac;
                    tev = sh_tev;
                    v  = v  + frac * (vn  - v);
                    iC = iC + frac * (in2 - iC);
                    s  = s  + frac * (sn2 - s);
                    yv = v; yi = iC; ys = s;
                    em = (sn2 > 0.0f);
                    done = true;
                    break;
                } else {
                    v = vn; iC = in2; s = sn2;
                    tcur += dt;
                }
            }
            if (!done) { yv = v; yi = iC; ys = s; tev = t1f; }
        }

        // ---- first spiking neuron index (min index where em) ----
        {
            int m = em ? n : NN;
            #pragma unroll
            for (int o = 16; o > 0; o >>= 1)
                m = min(m, __shfl_down_sync(0xffffffffu, m, o));
            __syncthreads();               // WAR protection on sh_i reuse
            if (lane == 0) sh_i[wid] = m;
            __syncthreads();
            if (n == 0) {
                int mm = sh_i[0];
                #pragma unroll
                for (int j = 1; j < 8; ++j) mm = min(mm, sh_i[j]);
                sh_eidx = mm;
            }
            __syncthreads();
        }
        const int eidx = done ? sh_eidx : 0;   // clamp for safe (predicated) load
        const float wrow = done ? w[eidx * NN + n] : 0.0f;

        // ---- outputs for this round ----
        if (n == 0) out[OUT_TIMES + samp * NROUND + k] = tev;
        {
            float* vp = out + OUT_VALS + ((size_t)(samp * NROUND + k) * NN + n) * 3;
            vp[0] = yv; vp[1] = yi; vp[2] = ys;
            out[OUT_MARKS + (size_t)(samp * NROUND + k) * NN + n] = em ? 1.0f : 0.0f;
        }

        // ---- reset for next round ----
        v  = yv - (em ? 1.0f : 0.0f);
        iC = yi + wrow;
        float srs = em ? reset_s[(size_t)k * NSAMP * NN + samp * NN + n] : ys;
        s  = fminf(srs, 0.0f);
        t0s = tev;
    }
}

extern "C" void kernel_launch(void* const* d_in, const int* in_sizes, int n_in,
                              void* d_out, int out_size) {
    const float* ic      = (const float*)d_in[0];  // input_current [256]
    const float* w       = (const float*)d_in[1];  // w [256,256]
    const float* mu      = (const float*)d_in[2];  // mu [2]
    const float* v0      = (const float*)d_in[3];  // v0 [256]
    const float* i0      = (const float*)d_in[4];  // i0 [256]
    const float* s0      = (const float*)d_in[5];  // s0 [512,256]
    const float* reset_s = (const float*)d_in[6];  // reset_s [32,512,256]
    const int*   t1      = (const int*)d_in[7];    // t1 scalar
    float* out = (float*)d_out;

    (void)in_sizes; (void)n_in; (void)out_size;
    snn_kernel<<<NSAMP, NN>>>(ic, w, mu, v0, i0, s0, reset_s, t1, out);
}

// round 6
// speedup vs baseline: 1.0447x; 1.0447x over previous
#include <cuda_runtime.h>
#include <math.h>

#define NN      256      // neurons
#define NSAMP   512      // samples
#define NROUND  32       // MAX_SPIKES rounds
#define NSTEP   32       // RK4 steps per round

// flattened output offsets (all float32)
#define OUT_TIMES 0
#define OUT_VALS  (NSAMP * NROUND)                       // 16384
#define OUT_MARKS (OUT_VALS + NSAMP * NROUND * NN * 3)   // 12599296

__global__ __launch_bounds__(NN)
void snn_kernel(const float* __restrict__ ic,      // [256]
                const float* __restrict__ w,       // [256,256]
                const float* __restrict__ mu,      // [2]
                const float* __restrict__ v0g,     // [256]
                const float* __restrict__ i0g,     // [256]
                const float* __restrict__ s0g,     // [512,256]
                const float* __restrict__ reset_s, // [32,512,256]
                const int*   __restrict__ t1p,     // scalar
                float* __restrict__ out)
{
    const int samp = blockIdx.x;
    const int n    = threadIdx.x;
    const int lane = n & 31;
    const int wid  = n >> 5;

    __shared__ float sh_v[8], sh_p[8];
    __shared__ int   sh_i[8], sh_m[8];
    __shared__ float sh_frac, sh_tev;
    __shared__ int   sh_eidx;

    const float t1f = (float)(*t1p);
    const float mu1 = mu[0];
    const float mu2 = mu[1];
    const float icn = ic[n];

    float v  = v0g[n];
    float iC = i0g[n];
    float s  = s0g[samp * NN + n];
    float t0s = 0.0f;

    for (int k = 0; k < NROUND; ++k) {
        const float dt = (t1f - t0s) * (1.0f / (float)NSTEP);
        bool  done = false;
        float tev  = t1f;
        float yv = v, yi = iC, ys = s;
        bool  em = false;

        if (dt > 0.0f) {
            float tcur = t0s;
            const float h  = dt;
            const float hh = 0.5f * h;
            const float h6 = h * (1.0f / 6.0f);
            for (int st = 0; st < NSTEP; ++st) {
                // ---- RK4 step (s does not feed back into v,i) ----
                float dv1 = mu1 * (iC + icn - v);
                float di1 = -mu2 * iC;
                float ds1 = 1.0f / (1.0f + expf(-v));
                float v2 = v + hh * dv1, i2 = iC + hh * di1;
                float dv2 = mu1 * (i2 + icn - v2);
                float di2 = -mu2 * i2;
                float ds2 = 1.0f / (1.0f + expf(-v2));
                float v3 = v + hh * dv2, i3 = iC + hh * di2;
                float dv3 = mu1 * (i3 + icn - v3);
                float di3 = -mu2 * i3;
                float ds3 = 1.0f / (1.0f + expf(-v3));
                float v4 = v + h * dv3, i4 = iC + h * di3;
                float dv4 = mu1 * (i4 + icn - v4);
                float di4 = -mu2 * i4;
                float ds4 = 1.0f / (1.0f + expf(-v4));
                float vn  = v  + h6 * (dv1 + 2.0f * dv2 + 2.0f * dv3 + dv4);
                float in2 = iC + h6 * (di1 + 2.0f * di2 + 2.0f * di3 + di4);
                float sn2 = s  + h6 * (ds1 + 2.0f * ds2 + 2.0f * ds3 + ds4);

                // ---- cheap trigger check: one BAR.RED per step ----
                const int trig = __syncthreads_or(sn2 > 0.0f);

                if (!trig) {
                    v = vn; iC = in2; s = sn2;
                    tcur += dt;
                    continue;
                }

                // ---- trigger path (once per round): fused argmax(sn2) with
                //      payload (s_prev, idx; ties -> lower idx) + min spiking idx ----
                {
                    float rv = sn2, rp = s;
                    int   ri = n;
                    int   rm = (sn2 > 0.0f) ? n : NN;
                    #pragma unroll
                    for (int o = 16; o > 0; o >>= 1) {
                        float ov = __shfl_down_sync(0xffffffffu, rv, o);
                        float op = __shfl_down_sync(0xffffffffu, rp, o);
                        int   oi = __shfl_down_sync(0xffffffffu, ri, o);
                        int   om = __shfl_down_sync(0xffffffffu, rm, o);
                        if (ov > rv || (ov == rv && oi < ri)) { rv = ov; rp = op; ri = oi; }
                        rm = min(rm, om);
                    }
                    if (lane == 0) { sh_v[wid] = rv; sh_p[wid] = rp; sh_i[wid] = ri; sh_m[wid] = rm; }
                    __syncthreads();
                    if (wid == 0) {
                        float rv2 = (lane < 8) ? sh_v[lane] : -INFINITY;
                        float rp2 = (lane < 8) ? sh_p[lane] : 0.0f;
                        int   ri2 = (lane < 8) ? sh_i[lane] : NN;
                        int   rm2 = (lane < 8) ? sh_m[lane] : NN;
                        #pragma unroll
                        for (int o = 4; o > 0; o >>= 1) {
                            float ov = __shfl_down_sync(0xffffffffu, rv2, o);
                            float op = __shfl_down_sync(0xffffffffu, rp2, o);
                            int   oi = __shfl_down_sync(0xffffffffu, ri2, o);
                            int   om = __shfl_down_sync(0xffffffffu, rm2, o);
                            if (ov > rv2 || (ov == rv2 && oi < ri2)) { rv2 = ov; rp2 = op; ri2 = oi; }
                            rm2 = min(rm2, om);
                        }
                        if (lane == 0) {
                            float frac = rp2 / (rp2 - rv2 + 1e-12f);
                            frac = fminf(fmaxf(frac, 0.0f), 1.0f);
                            sh_frac = frac;
                            sh_tev  = tcur + frac * dt;
                            sh_eidx = rm2;
                        }
                    }
                    __syncthreads();
                }

                const float frac = sh_frac;
                tev = sh_tev;
                v  = v  + frac * (vn  - v);
                iC = iC + frac * (in2 - iC);
                s  = s  + frac * (sn2 - s);
                yv = v; yi = iC; ys = s;
                em = (sn2 > 0.0f);
                done = true;
                break;
            }
            if (!done) { yv = v; yi = iC; ys = s; tev = t1f; }
        }

        const int eidx = done ? sh_eidx : 0;   // clamp for safe load
        const float wrow = done ? w[eidx * NN + n] : 0.0f;

        // ---- outputs for this round ----
        if (n == 0) out[OUT_TIMES + samp * NROUND + k] = tev;
        {
            float* vp = out + OUT_VALS + ((size_t)(samp * NROUND + k) * NN + n) * 3;
            vp[0] = yv; vp[1] = yi; vp[2] = ys;
            out[OUT_MARKS + (size_t)(samp * NROUND + k) * NN + n] = em ? 1.0f : 0.0f;
        }

        // ---- reset for next round ----
        v  = yv - (em ? 1.0f : 0.0f);
        iC = yi + wrow;
        float srs = em ? reset_s[(size_t)k * NSAMP * NN + samp * NN + n] : ys;
        s  = fminf(srs, 0.0f);
        t0s = tev;

        // WAR protection: sh_eidx / sh_* must not be overwritten by the next
        // round's trigger path before all threads have read them.
        __syncthreads();
    }
}

extern "C" void kernel_launch(void* const* d_in, const int* in_sizes, int n_in,
                              void* d_out, int out_size) {
    const float* ic      = (const float*)d_in[0];  // input_current [256]
    const float* w       = (const float*)d_in[1];  // w [256,256]
    const float* mu      = (const float*)d_in[2];  // mu [2]
    const float* v0      = (const float*)d_in[3];  // v0 [256]
    const float* i0      = (const float*)d_in[4];  // i0 [256]
    const float* s0      = (const float*)d_in[5];  // s0 [512,256]
    const float* reset_s = (const float*)d_in[6];  // reset_s [32,512,256]
    const int*   t1      = (const int*)d_in[7];    // t1 scalar
    float* out = (float*)d_out;

    (void)in_sizes; (void)n_in; (void)out_size;
    snn_kernel<<<NSAMP, NN>>>(ic, w, mu, v0, i0, s0, reset_s, t1, out);
}

// round 7
// speedup vs baseline: 1.2209x; 1.1687x over previous
#include <cuda_runtime.h>
#include <math.h>

#define NN      256      // neurons
#define NSAMP   512      // samples
#define NROUND  32       // MAX_SPIKES rounds
#define NSTEP   32       // RK4 steps per round

// flattened output offsets (all float32)
#define OUT_TIMES 0
#define OUT_VALS  (NSAMP * NROUND)                       // 16384
#define OUT_MARKS (OUT_VALS + NSAMP * NROUND * NN * 3)   // 12599296

// coefficient triple: value = .v * v0 + .i * i0 + .c * icn
struct C3 { float v, i, c; };
__device__ __forceinline__ C3 c3(float a, float b, float c) { return {a, b, c}; }
__device__ __forceinline__ C3 add(C3 a, C3 b) { return {a.v + b.v, a.i + b.i, a.c + b.c}; }
__device__ __forceinline__ C3 sub(C3 a, C3 b) { return {a.v - b.v, a.i - b.i, a.c - b.c}; }
__device__ __forceinline__ C3 scl(float s, C3 a) { return {s * a.v, s * a.i, s * a.c}; }

__device__ __forceinline__ float fast_sigmoid(float x) {
    // 1/(1+exp(-x)) via MUFU.EX2 + MUFU.RCP
    float e = __expf(-x);
    return __fdividef(1.0f, 1.0f + e);
}

__global__ __launch_bounds__(NN)
void snn_kernel(const float* __restrict__ ic,      // [256]
                const float* __restrict__ w,       // [256,256]
                const float* __restrict__ mu,      // [2]
                const float* __restrict__ v0g,     // [256]
                const float* __restrict__ i0g,     // [256]
                const float* __restrict__ s0g,     // [512,256]
                const float* __restrict__ reset_s, // [32,512,256]
                const int*   __restrict__ t1p,     // scalar
                float* __restrict__ out)
{
    const int samp = blockIdx.x;
    const int n    = threadIdx.x;
    const int lane = n & 31;
    const int wid  = n >> 5;

    __shared__ float sh_v[8], sh_p[8];
    __shared__ int   sh_i[8], sh_m[8];
    __shared__ float sh_frac, sh_tev;
    __shared__ int   sh_eidx;

    const float t1f = (float)(*t1p);
    const float mu1 = mu[0];
    const float mu2 = mu[1];
    const float icn = ic[n];

    float v  = v0g[n];
    float iC = i0g[n];
    float s  = s0g[samp * NN + n];
    float t0s = 0.0f;

    for (int k = 0; k < NROUND; ++k) {
        const float dt = (t1f - t0s) * (1.0f / (float)NSTEP);

        // prefetch the reset row for this round off the critical path
        const float rsk = reset_s[(size_t)k * NSAMP * NN + samp * NN + n];

        bool  done = false;
        float tev  = t1f;
        float yv = v, yi = iC, ys = s;
        bool  em = false;

        if (dt > 0.0f) {
            const float h  = dt;
            const float hh = 0.5f * h;
            const float h6 = h * (1.0f / 6.0f);

            // ---- per-round affine RK4 stage coefficients (thread-uniform) ----
            // basis: (v, i, icn).  dv = mu1*(i + icn - v), di = -mu2*i
            const C3 V   = c3(1.f, 0.f, 0.f);
            const C3 I   = c3(0.f, 1.f, 0.f);
            const C3 ONE = c3(0.f, 0.f, 1.f);
            C3 k1v = scl(mu1, sub(add(I, ONE), V));
            C3 k1i = scl(-mu2, I);
            C3 v2c = add(V, scl(hh, k1v));
            C3 i2c = add(I, scl(hh, k1i));
            C3 k2v = scl(mu1, sub(add(i2c, ONE), v2c));
            C3 k2i = scl(-mu2, i2c);
            C3 v3c = add(V, scl(hh, k2v));
            C3 i3c = add(I, scl(hh, k2i));
            C3 k3v = scl(mu1, sub(add(i3c, ONE), v3c));
            C3 k3i = scl(-mu2, i3c);
            C3 v4c = add(V, scl(h, k3v));
            C3 i4c = add(I, scl(h, k3i));
            C3 k4v = scl(mu1, sub(add(i4c, ONE), v4c));
            C3 k4i = scl(-mu2, i4c);
            C3 vnc = add(V, scl(h6, add(add(k1v, k4v), scl(2.f, add(k2v, k3v)))));
            C3 inc = add(I, scl(h6, add(add(k1i, k4i), scl(2.f, add(k2i, k3i)))));
            // fold per-thread icn into constants
            const float v2cc = v2c.c * icn, v3cc = v3c.c * icn;
            const float v4cc = v4c.c * icn, vncc = vnc.c * icn;
            const float pin  = inc.i;   // in2 = pin * iC  (inc.v == inc.c == 0)

            float tcur = t0s;
            for (int st = 0; st < NSTEP; ++st) {
                // ---- RK4 step via precomputed affine stages (all independent) ----
                float v2  = fmaf(v2c.v, v, fmaf(v2c.i, iC, v2cc));
                float v3  = fmaf(v3c.v, v, fmaf(v3c.i, iC, v3cc));
                float v4  = fmaf(v4c.v, v, fmaf(v4c.i, iC, v4cc));
                float vn  = fmaf(vnc.v, v, fmaf(vnc.i, iC, vncc));
                float in2 = pin * iC;
                float ds1 = fast_sigmoid(v);
                float ds2 = fast_sigmoid(v2);
                float ds3 = fast_sigmoid(v3);
                float ds4 = fast_sigmoid(v4);
                float sn2 = fmaf(h6, (ds1 + ds4) + 2.0f * (ds2 + ds3), s);

                // ---- cheap trigger check: one BAR.RED per step ----
                const int trig = __syncthreads_or(sn2 > 0.0f);

                if (!trig) {
                    v = vn; iC = in2; s = sn2;
                    tcur += dt;
                    continue;
                }

                // ---- trigger path (once per round): fused argmax(sn2) with
                //      payload (s_prev, idx; ties -> lower idx) + min spiking idx ----
                {
                    float rv = sn2, rp = s;
                    int   ri = n;
                    int   rm = (sn2 > 0.0f) ? n : NN;
                    #pragma unroll
                    for (int o = 16; o > 0; o >>= 1) {
                        float ov = __shfl_down_sync(0xffffffffu, rv, o);
                        float op = __shfl_down_sync(0xffffffffu, rp, o);
                        int   oi = __shfl_down_sync(0xffffffffu, ri, o);
                        int   om = __shfl_down_sync(0xffffffffu, rm, o);
                        if (ov > rv || (ov == rv && oi < ri)) { rv = ov; rp = op; ri = oi; }
                        rm = min(rm, om);
                    }
                    if (lane == 0) { sh_v[wid] = rv; sh_p[wid] = rp; sh_i[wid] = ri; sh_m[wid] = rm; }
                    __syncthreads();
                    if (wid == 0) {
                        float rv2 = (lane < 8) ? sh_v[lane] : -INFINITY;
                        float rp2 = (lane < 8) ? sh_p[lane] : 0.0f;
                        int   ri2 = (lane < 8) ? sh_i[lane] : NN;
                        int   rm2 = (lane < 8) ? sh_m[lane] : NN;
                        #pragma unroll
                        for (int o = 4; o > 0; o >>= 1) {
                            float ov = __shfl_down_sync(0xffffffffu, rv2, o);
                            float op = __shfl_down_sync(0xffffffffu, rp2, o);
                            int   oi = __shfl_down_sync(0xffffffffu, ri2, o);
                            int   om = __shfl_down_sync(0xffffffffu, rm2, o);
                            if (ov > rv2 || (ov == rv2 && oi < ri2)) { rv2 = ov; rp2 = op; ri2 = oi; }
                            rm2 = min(rm2, om);
                        }
                        if (lane == 0) {
                            float frac = rp2 / (rp2 - rv2 + 1e-12f);
                            frac = fminf(fmaxf(frac, 0.0f), 1.0f);
                            sh_frac = frac;
                            sh_tev  = tcur + frac * dt;
                            sh_eidx = rm2;
                        }
                    }
                    __syncthreads();
                }

                const float frac = sh_frac;
                tev = sh_tev;
                v  = v  + frac * (vn  - v);
                iC = iC + frac * (in2 - iC);
                s  = s  + frac * (sn2 - s);
                yv = v; yi = iC; ys = s;
                em = (sn2 > 0.0f);
                done = true;
                break;
            }
            if (!done) { yv = v; yi = iC; ys = s; tev = t1f; }
        }

        const int eidx = done ? sh_eidx : 0;   // clamp for safe load
        const float wrow = done ? w[eidx * NN + n] : 0.0f;

        // ---- outputs for this round ----
        if (n == 0) out[OUT_TIMES + samp * NROUND + k] = tev;
        {
            float* vp = out + OUT_VALS + ((size_t)(samp * NROUND + k) * NN + n) * 3;
            vp[0] = yv; vp[1] = yi; vp[2] = ys;
            out[OUT_MARKS + (size_t)(samp * NROUND + k) * NN + n] = em ? 1.0f : 0.0f;
        }

        // ---- reset for next round ----
        v  = yv - (em ? 1.0f : 0.0f);
        iC = yi + wrow;
        float srs = em ? rsk : ys;
        s  = fminf(srs, 0.0f);
        t0s = tev;

        // WAR protection: sh_* must not be overwritten by the next round's
        // trigger path before all threads have consumed sh_eidx.
        __syncthreads();
    }
}

extern "C" void kernel_launch(void* const* d_in, const int* in_sizes, int n_in,
                              void* d_out, int out_size) {
    const float* ic      = (const float*)d_in[0];  // input_current [256]
    const float* w       = (const float*)d_in[1];  // w [256,256]
    const float* mu      = (const float*)d_in[2];  // mu [2]
    const float* v0      = (const float*)d_in[3];  // v0 [256]
    const float* i0      = (const float*)d_in[4];  // i0 [256]
    const float* s0      = (const float*)d_in[5];  // s0 [512,256]
    const float* reset_s = (const float*)d_in[6];  // reset_s [32,512,256]
    const int*   t1      = (const int*)d_in[7];    // t1 scalar
    float* out = (float*)d_out;

    (void)in_sizes; (void)n_in; (void)out_size;
    snn_kernel<<<NSAMP, NN>>>(ic, w, mu, v0, i0, s0, reset_s, t1, out);
}